// round 16
// baseline (speedup 1.0000x reference)
#include <cuda_runtime.h>
#include <cuda_fp16.h>

typedef unsigned long long u64;
typedef unsigned int u32;

#define B_  32
#define C_  64
#define CP  (C_ / 2)
#define T_  20000
#define K1  100
#define K2  50
#define T1  19901
#define T1P 19904             /* padded row stride in halves */
#define T2  19852

/* ---- Kernel A (tf32 k8 MMA, cp.async fill, direct store) ---- */
#define THA 128
#define TA_BLK 4096
#define NTILE_A 5
#define XWIN 4200
#define XS_WORDS 4464

/* ---- Kernel C config (round-10: sa2 + group sums) ---- */
#define THC 256
#define RC  8
#define TC  (THC * RC)        /* 2048 */
#define NTILE_C 10
#define NAC (TC + K2 - 1)     /* 2097 */
#define NGRP 263

/* device scratch */
__device__ __half g_yh[(size_t)B_ * C_ * T1P];
__device__ float g_ps[C_ * B_ * NTILE_A];
__device__ float g_pq[C_ * B_ * NTILE_A];
__device__ float g_scale[C_];
__device__ float g_shift[C_];

__device__ __forceinline__ u32 f2tf32(float f) {
    u32 r;
    asm("cvt.rna.tf32.f32 %0, %1;" : "=r"(r) : "f"(f));
    return r;
}

#define MMA8(D, a0, a1, a2, a3, b0, b1) \
    asm("mma.sync.aligned.m16n8k8.row.col.f32.tf32.tf32.f32 " \
        "{%0,%1,%2,%3}, {%4,%5,%6,%7}, {%8,%9}, {%0,%1,%2,%3};" \
        : "+f"(D[0]), "+f"(D[1]), "+f"(D[2]), "+f"(D[3]) \
        : "r"(a0), "r"(a1), "r"(a2), "r"(a3), "r"(b0), "r"(b1))

/* stride-8 access swizzle: step 9 (coprime 32) */
__device__ __forceinline__ int swz8(int i) { return i + (i >> 3); }

/* =====================================================================
 * Kernel A: tf32 k8 Toeplitz GEMM, cp.async fill, direct half2 stores
 * (no ys staging, two fewer barriers).
 * ===================================================================== */
__global__ void __launch_bounds__(THA, 8)
conv_band_mma(const float* __restrict__ x, const float* __restrict__ w_band)
{
    __shared__ u32   xs[XS_WORDS];
    __shared__ float ws[K1];
    __shared__ float rsum[4], rsq[4];

    const int tile = blockIdx.x;
    const int c    = blockIdx.y;
    const int b    = blockIdx.z;
    const int tid  = threadIdx.x;
    const int t0   = tile * TA_BLK;

    const float* __restrict__ xp = x + ((size_t)(b * C_ + c)) * T_;
    if (tid < K1) ws[tid] = w_band[c * K1 + tid];

    {
        const u32 sbase = (u32)__cvta_generic_to_shared(xs);
        if (t0 + XWIN <= T_) {
            for (int j = tid; j < XWIN / 4; j += THA) {
                const int i = 4 * j;
                const u32 dst = sbase + 4u * (u32)(i + 4 * (i >> 6));
                const float* src = xp + t0 + i;
                asm volatile("cp.async.ca.shared.global [%0], [%1], 16;"
                             :: "r"(dst), "l"(src) : "memory");
            }
        } else {
            for (int j = tid; j < XWIN / 4; j += THA) {
                const int i = 4 * j;
                const u32 dst = sbase + 4u * (u32)(i + 4 * (i >> 6));
                const int gt = t0 + i;
                int nb = (T_ - gt) * 4;
                nb = nb < 0 ? 0 : (nb > 16 ? 16 : nb);
                const float* src = xp + (gt < T_ ? gt : 0);
                asm volatile("cp.async.ca.shared.global [%0], [%1], 16, %2;"
                             :: "r"(dst), "l"(src), "r"(nb) : "memory");
            }
        }
        asm volatile("cp.async.commit_group;" ::: "memory");
        asm volatile("cp.async.wait_group 0;" ::: "memory");
    }
    __syncthreads();

    const int wrp  = tid >> 5;
    const int lane = tid & 31;
    const int g    = lane >> 2;
    const int cl   = lane & 3;

    u32 bb0[14], bb1[14];
#pragma unroll
    for (int j = 0; j < 14; ++j) {
        const int i0 = 8 * j + cl - g;
        const int i1 = i0 + 4;
        bb0[j] = (i0 >= 0 && i0 < K1) ? f2tf32(ws[i0]) : 0u;
        bb1[j] = (i1 >= 0 && i1 < K1) ? f2tf32(ws[i1]) : 0u;
    }

    const u32* px = xs + 1088 * wrp + 68 * g + cl;

    float D[8][4];
#pragma unroll
    for (int d = 0; d < 8; ++d)
#pragma unroll
        for (int e = 0; e < 4; ++e) D[d][e] = 0.f;

#pragma unroll
    for (int ks8 = 0; ks8 < 21; ++ks8) {
        const int ofs = 8 * ks8 + 4 * (ks8 >> 3);
        const u32 a0 = px[ofs];
        const u32 a2 = px[ofs + 4];
        const u32 a1 = px[ofs + 544];
        const u32 a3 = px[ofs + 548];
#pragma unroll
        for (int d = 0; d < 8; ++d) {
            const int j = ks8 - d;
            if (j >= 0 && j < 14)
                MMA8(D[d], a0, a1, a2, a3, bb0[j], bb1[j]);
        }
    }

    /* stats from fp32 accumulators; interior fast path */
    const int tbw = t0 + 1024 * wrp;
    float s = 0.f, q = 0.f;
    if (t0 + TA_BLK <= T1) {
#pragma unroll
        for (int d = 0; d < 8; ++d) {
#pragma unroll
            for (int e = 0; e < 4; ++e) {
                const float v = D[d][e];
                s += v;
                q = fmaf(v, v, q);
            }
        }
    } else {
#pragma unroll
        for (int d = 0; d < 8; ++d) {
            const int l0 = 64 * g + 8 * d + 2 * cl;
            const int l1 = l0 + 512;
            const float v0 = D[d][0], v1 = D[d][1], v2 = D[d][2], v3 = D[d][3];
            if (tbw + l0     < T1) { s += v0; q = fmaf(v0, v0, q); }
            if (tbw + l0 + 1 < T1) { s += v1; q = fmaf(v1, v1, q); }
            if (tbw + l1     < T1) { s += v2; q = fmaf(v2, v2, q); }
            if (tbw + l1 + 1 < T1) { s += v3; q = fmaf(v3, v3, q); }
        }
    }

    /* direct half2 stores: thread (g,cl), delta d owns half2 at local
       offset 64g+8d+2cl -> quad-contiguous 16B runs, sector-coalesced. */
    {
        __half2* __restrict__ yg2 =
            reinterpret_cast<__half2*>(g_yh + ((size_t)(b * C_ + c)) * T1P);
        const int ybase = (tbw >> 1) + 32 * g + cl;   /* half2 units */
        if (t0 + TA_BLK <= T1) {
#pragma unroll
            for (int d = 0; d < 8; ++d) {
                yg2[ybase + 4 * d]       = __floats2half2_rn(D[d][0], D[d][1]);
                yg2[ybase + 4 * d + 256] = __floats2half2_rn(D[d][2], D[d][3]);
            }
        } else {
#pragma unroll
            for (int d = 0; d < 8; ++d) {
                const int l0 = 64 * g + 8 * d + 2 * cl;
                const int l1 = l0 + 512;
                if (tbw + l0 < T1)
                    yg2[ybase + 4 * d]       = __floats2half2_rn(D[d][0], D[d][1]);
                if (tbw + l1 < T1)
                    yg2[ybase + 4 * d + 256] = __floats2half2_rn(D[d][2], D[d][3]);
            }
        }
    }

#pragma unroll
    for (int o = 16; o; o >>= 1) {
        s += __shfl_down_sync(0xffffffffu, s, o);
        q += __shfl_down_sync(0xffffffffu, q, o);
    }
    if (lane == 0) { rsum[wrp] = s; rsq[wrp] = q; }
    __syncthreads();

    if (tid == 0) {
        const int pidx = (c * B_ + b) * NTILE_A + tile;
        g_ps[pidx] = rsum[0] + rsum[1] + rsum[2] + rsum[3];
        g_pq[pidx] = rsq[0] + rsq[1] + rsq[2] + rsq[3];
    }
}

/* =====================================================================
 * Kernel B: per-channel stats -> scale/shift
 * ===================================================================== */
__global__ void __launch_bounds__(256)
stats_kernel(const float* __restrict__ gamma, const float* __restrict__ beta)
{
    const int c   = blockIdx.x;
    const int tid = threadIdx.x;
    const int NP  = B_ * NTILE_A;

    float s = 0.f, q = 0.f;
    for (int i = tid; i < NP; i += 256) {
        s += g_ps[c * NP + i];
        q += g_pq[c * NP + i];
    }
#pragma unroll
    for (int o = 16; o; o >>= 1) {
        s += __shfl_down_sync(0xffffffffu, s, o);
        q += __shfl_down_sync(0xffffffffu, q, o);
    }
    __shared__ float rs[8], rq[8];
    const int w = tid >> 5, l = tid & 31;
    if (l == 0) { rs[w] = s; rq[w] = q; }
    __syncthreads();
    if (tid == 0) {
        float S = 0.f, Q = 0.f;
#pragma unroll
        for (int i = 0; i < 8; ++i) { S += rs[i]; Q += rq[i]; }
        const float n    = (float)B_ * (float)T1;
        const float mean = S / n;
        const float var  = Q / n - mean * mean;
        const float sc   = gamma[c] * rsqrtf(var + 1e-5f);
        g_scale[c] = sc;
        g_shift[c] = beta[c] - mean * sc;
    }
}

/* =====================================================================
 * Kernel C: round-10 version (best measured): affine + abs + box
 * lowpass, group sums computed during fill -> 8-load warm-up.
 * ===================================================================== */
__global__ void __launch_bounds__(THC)
lowpass_kernel(const float* __restrict__ w_low, const float* __restrict__ b_low,
               float* __restrict__ out)
{
    __shared__ float2 sa2[NAC + (NAC >> 3) + 2];
    __shared__ float2 grp2[NGRP + 1];

    const int tile = blockIdx.x;
    const int cc   = blockIdx.y;
    const int b    = blockIdx.z;
    const int tid  = threadIdx.x;
    const int t0   = tile * TC;

    const float2 sc = make_float2(g_scale[2 * cc], g_scale[2 * cc + 1]);
    const float2 sh = make_float2(g_shift[2 * cc], g_shift[2 * cc + 1]);
    const __half* __restrict__ yp0 = g_yh + ((size_t)(b * C_ + 2 * cc)) * T1P;
    const __half* __restrict__ yp1 = yp0 + T1P;

    for (int j = tid; j < NGRP; j += THC) {
        const int i0 = 8 * j;
        const int gt = t0 + i0;
        float2 gs = make_float2(0.f, 0.f);
        if (gt + 7 < T1 && i0 + 7 < NAC) {
            uint4 u0 = *reinterpret_cast<const uint4*>(yp0 + gt);
            uint4 u1 = *reinterpret_cast<const uint4*>(yp1 + gt);
            const __half2* h0 = reinterpret_cast<const __half2*>(&u0);
            const __half2* h1 = reinterpret_cast<const __half2*>(&u1);
#pragma unroll
            for (int p = 0; p < 4; ++p) {
                float2 v0 = __half22float2(h0[p]);
                float2 v1 = __half22float2(h1[p]);
                float2 va = make_float2(fabsf(fmaf(v0.x, sc.x, sh.x)),
                                        fabsf(fmaf(v1.x, sc.y, sh.y)));
                float2 vb = make_float2(fabsf(fmaf(v0.y, sc.x, sh.x)),
                                        fabsf(fmaf(v1.y, sc.y, sh.y)));
                sa2[swz8(i0 + 2 * p)]     = va;
                sa2[swz8(i0 + 2 * p + 1)] = vb;
                gs.x += va.x + vb.x;
                gs.y += va.y + vb.y;
            }
        } else {
#pragma unroll
            for (int e = 0; e < 8; ++e) {
                if (i0 + e < NAC) {
                    float a0 = (gt + e < T1) ? __half2float(yp0[gt + e]) : 0.f;
                    float a1 = (gt + e < T1) ? __half2float(yp1[gt + e]) : 0.f;
                    float2 v = make_float2(fabsf(fmaf(a0, sc.x, sh.x)),
                                           fabsf(fmaf(a1, sc.y, sh.y)));
                    sa2[swz8(i0 + e)] = v;
                    gs.x += v.x;
                    gs.y += v.y;
                }
            }
        }
        grp2[j] = gs;
    }
    __syncthreads();

    const int base = tid * RC;
    const float wl0 = w_low[(2 * cc) * K2];
    const float wl1 = w_low[(2 * cc + 1) * K2];
    const float bl0 = b_low[2 * cc];
    const float bl1 = b_low[2 * cc + 1];

    float2 s;
    {
        float2 g0 = grp2[tid],     g1 = grp2[tid + 1];
        float2 g2 = grp2[tid + 2], g3 = grp2[tid + 3];
        float2 g4 = grp2[tid + 4], g5 = grp2[tid + 5];
        float2 e0 = sa2[swz8(base + 48)];
        float2 e1 = sa2[swz8(base + 49)];
        s.x = ((g0.x + g1.x) + (g2.x + g3.x)) + ((g4.x + g5.x) + (e0.x + e1.x));
        s.y = ((g0.y + g1.y) + (g2.y + g3.y)) + ((g4.y + g5.y) + (e0.y + e1.y));
    }

    float2 z[RC];
    z[0] = s;
#pragma unroll
    for (int r = 1; r < RC; ++r) {
        float2 a = sa2[swz8(base + r + K2 - 1)];
        float2 d = sa2[swz8(base + r - 1)];
        s.x += a.x - d.x;
        s.y += a.y - d.y;
        z[r] = s;
    }

    float* __restrict__ o0 = out + ((size_t)(b * C_ + 2 * cc)) * T2 + t0 + base;
    float* __restrict__ o1 = o0 + T2;

    if (t0 + TC <= T2) {
        float4* __restrict__ o0v = reinterpret_cast<float4*>(o0);
        float4* __restrict__ o1v = reinterpret_cast<float4*>(o1);
#pragma unroll
        for (int g2i = 0; g2i < RC / 4; ++g2i) {
            o0v[g2i] = make_float4(fmaf(z[4 * g2i].x, wl0, bl0), fmaf(z[4 * g2i + 1].x, wl0, bl0),
                                   fmaf(z[4 * g2i + 2].x, wl0, bl0), fmaf(z[4 * g2i + 3].x, wl0, bl0));
            o1v[g2i] = make_float4(fmaf(z[4 * g2i].y, wl1, bl1), fmaf(z[4 * g2i + 1].y, wl1, bl1),
                                   fmaf(z[4 * g2i + 2].y, wl1, bl1), fmaf(z[4 * g2i + 3].y, wl1, bl1));
        }
    } else {
#pragma unroll
        for (int r = 0; r < RC; ++r) {
            if (t0 + base + r < T2) {
                o0[r] = fmaf(z[r].x, wl0, bl0);
                o1[r] = fmaf(z[r].y, wl1, bl1);
            }
        }
    }
}

/* ===================================================================== */
extern "C" void kernel_launch(void* const* d_in, const int* in_sizes, int n_in,
                              void* d_out, int out_size)
{
    const float* x      = (const float*)d_in[0];
    const float* w_band = (const float*)d_in[1];
    const float* gamma  = (const float*)d_in[2];
    const float* beta   = (const float*)d_in[3];
    const float* w_low  = (const float*)d_in[4];
    const float* b_low  = (const float*)d_in[5];
    float* out = (float*)d_out;

    dim3 ga(NTILE_A, C_, B_);
    conv_band_mma<<<ga, THA>>>(x, w_band);

    stats_kernel<<<C_, 256>>>(gamma, beta);

    dim3 gc(NTILE_C, CP, B_);
    lowpass_kernel<<<gc, THC>>>(w_low, b_low, out);
}

// round 17
// speedup vs baseline: 1.0549x; 1.0549x over previous
#include <cuda_runtime.h>
#include <cuda_fp16.h>

typedef unsigned long long u64;
typedef unsigned int u32;

#define B_  32
#define C_  64
#define CP  (C_ / 2)
#define T_  20000
#define K1  100
#define K2  50
#define T1  19901
#define T1P 19904             /* padded row stride in halves */
#define T2  19852

/* ---- Kernel A (tf32 k8 MMA, cp.async fill, staged store) ---- */
#define THA 128
#define TA_BLK 4096
#define NTILE_A 5
#define XWIN 4200
#define XS_WORDS 4464

/* ---- Kernel C (round-10 shape + inline stats) ---- */
#define THC 256
#define RC  8
#define TC  (THC * RC)        /* 2048 */
#define NTILE_C 10
#define NAC (TC + K2 - 1)     /* 2097 */
#define NGRP 263
#define NP_ (B_ * NTILE_A)    /* 160 partials per channel */

/* device scratch */
__device__ __half g_yh[(size_t)B_ * C_ * T1P];
__device__ float g_ps[C_ * NP_];
__device__ float g_pq[C_ * NP_];

__device__ __forceinline__ u32 f2tf32(float f) {
    u32 r;
    asm("cvt.rna.tf32.f32 %0, %1;" : "=r"(r) : "f"(f));
    return r;
}

#define MMA8(D, a0, a1, a2, a3, b0, b1) \
    asm("mma.sync.aligned.m16n8k8.row.col.f32.tf32.tf32.f32 " \
        "{%0,%1,%2,%3}, {%4,%5,%6,%7}, {%8,%9}, {%0,%1,%2,%3};" \
        : "+f"(D[0]), "+f"(D[1]), "+f"(D[2]), "+f"(D[3]) \
        : "r"(a0), "r"(a1), "r"(a2), "r"(a3), "r"(b0), "r"(b1))

/* stride-8 access swizzle: step 9 (coprime 32) */
__device__ __forceinline__ int swz8(int i) { return i + (i >> 3); }

/* =====================================================================
 * Kernel A: round-14 version (measured 57.2 us) — cp.async fill,
 * smem-staged coalesced fp16 store.
 * ===================================================================== */
__global__ void __launch_bounds__(THA, 8)
conv_band_mma(const float* __restrict__ x, const float* __restrict__ w_band)
{
    __shared__ u32   xs[XS_WORDS];
    __shared__ float ws[K1];
    __shared__ float rsum[4], rsq[4];
    __half2* ys = reinterpret_cast<__half2*>(xs);

    const int tile = blockIdx.x;
    const int c    = blockIdx.y;
    const int b    = blockIdx.z;
    const int tid  = threadIdx.x;
    const int t0   = tile * TA_BLK;

    const float* __restrict__ xp = x + ((size_t)(b * C_ + c)) * T_;
    if (tid < K1) ws[tid] = w_band[c * K1 + tid];

    {
        const u32 sbase = (u32)__cvta_generic_to_shared(xs);
        if (t0 + XWIN <= T_) {
            for (int j = tid; j < XWIN / 4; j += THA) {
                const int i = 4 * j;
                const u32 dst = sbase + 4u * (u32)(i + 4 * (i >> 6));
                const float* src = xp + t0 + i;
                asm volatile("cp.async.ca.shared.global [%0], [%1], 16;"
                             :: "r"(dst), "l"(src) : "memory");
            }
        } else {
            for (int j = tid; j < XWIN / 4; j += THA) {
                const int i = 4 * j;
                const u32 dst = sbase + 4u * (u32)(i + 4 * (i >> 6));
                const int gt = t0 + i;
                int nb = (T_ - gt) * 4;
                nb = nb < 0 ? 0 : (nb > 16 ? 16 : nb);
                const float* src = xp + (gt < T_ ? gt : 0);
                asm volatile("cp.async.ca.shared.global [%0], [%1], 16, %2;"
                             :: "r"(dst), "l"(src), "r"(nb) : "memory");
            }
        }
        asm volatile("cp.async.commit_group;" ::: "memory");
        asm volatile("cp.async.wait_group 0;" ::: "memory");
    }
    __syncthreads();

    const int wrp  = tid >> 5;
    const int lane = tid & 31;
    const int g    = lane >> 2;
    const int cl   = lane & 3;

    u32 bb0[14], bb1[14];
#pragma unroll
    for (int j = 0; j < 14; ++j) {
        const int i0 = 8 * j + cl - g;
        const int i1 = i0 + 4;
        bb0[j] = (i0 >= 0 && i0 < K1) ? f2tf32(ws[i0]) : 0u;
        bb1[j] = (i1 >= 0 && i1 < K1) ? f2tf32(ws[i1]) : 0u;
    }

    const u32* px = xs + 1088 * wrp + 68 * g + cl;

    float D[8][4];
#pragma unroll
    for (int d = 0; d < 8; ++d)
#pragma unroll
        for (int e = 0; e < 4; ++e) D[d][e] = 0.f;

#pragma unroll
    for (int ks8 = 0; ks8 < 21; ++ks8) {
        const int ofs = 8 * ks8 + 4 * (ks8 >> 3);
        const u32 a0 = px[ofs];
        const u32 a2 = px[ofs + 4];
        const u32 a1 = px[ofs + 544];
        const u32 a3 = px[ofs + 548];
#pragma unroll
        for (int d = 0; d < 8; ++d) {
            const int j = ks8 - d;
            if (j >= 0 && j < 14)
                MMA8(D[d], a0, a1, a2, a3, bb0[j], bb1[j]);
        }
    }

    const int tbw = t0 + 1024 * wrp;
    float s = 0.f, q = 0.f;
    if (t0 + TA_BLK <= T1) {
#pragma unroll
        for (int d = 0; d < 8; ++d) {
#pragma unroll
            for (int e = 0; e < 4; ++e) {
                const float v = D[d][e];
                s += v;
                q = fmaf(v, v, q);
            }
        }
    } else {
#pragma unroll
        for (int d = 0; d < 8; ++d) {
            const int l0 = 64 * g + 8 * d + 2 * cl;
            const int l1 = l0 + 512;
            const float v0 = D[d][0], v1 = D[d][1], v2 = D[d][2], v3 = D[d][3];
            if (tbw + l0     < T1) { s += v0; q = fmaf(v0, v0, q); }
            if (tbw + l0 + 1 < T1) { s += v1; q = fmaf(v1, v1, q); }
            if (tbw + l1     < T1) { s += v2; q = fmaf(v2, v2, q); }
            if (tbw + l1 + 1 < T1) { s += v3; q = fmaf(v3, v3, q); }
        }
    }

    __syncthreads();

#pragma unroll
    for (int d = 0; d < 8; ++d) {
        const int yb = 576 * wrp + 36 * g + cl;
        ys[yb + 4 * d]       = __floats2half2_rn(D[d][0], D[d][1]);
        ys[yb + 4 * d + 288] = __floats2half2_rn(D[d][2], D[d][3]);
    }

#pragma unroll
    for (int o = 16; o; o >>= 1) {
        s += __shfl_down_sync(0xffffffffu, s, o);
        q += __shfl_down_sync(0xffffffffu, q, o);
    }
    if (lane == 0) { rsum[wrp] = s; rsq[wrp] = q; }
    __syncthreads();

    __half* __restrict__ yg = g_yh + ((size_t)(b * C_ + c)) * T1P + t0;
#pragma unroll
    for (int jj = 0; jj < 4; ++jj) {
        const int r  = tid + 128 * jj;
        const int i2 = 4 * r;
        const int sw = i2 + 4 * (i2 >> 5);
        const int h0 = 8 * r;
        if (t0 + h0 + 7 < T1) {
            *reinterpret_cast<uint4*>(yg + h0) =
                *reinterpret_cast<const uint4*>(ys + sw);
        } else {
            const __half* yh = reinterpret_cast<const __half*>(ys + sw);
#pragma unroll
            for (int e = 0; e < 8; ++e)
                if (t0 + h0 + e < T1) yg[h0 + e] = yh[e];
        }
    }

    if (tid == 0) {
        const int pidx = (c * B_ + b) * NTILE_A + tile;
        g_ps[pidx] = rsum[0] + rsum[1] + rsum[2] + rsum[3];
        g_pq[pidx] = rsq[0] + rsq[1] + rsq[2] + rsq[3];
    }
}

/* =====================================================================
 * Kernel C: round-10 lowpass with INLINE per-block stats reduction
 * (kernel B eliminated; g_ps/g_pq are L2-resident, 41 KB).
 * ===================================================================== */
__global__ void __launch_bounds__(THC)
lowpass_kernel(const float* __restrict__ gamma, const float* __restrict__ beta,
               const float* __restrict__ w_low, const float* __restrict__ b_low,
               float* __restrict__ out)
{
    __shared__ float2 sa2[NAC + (NAC >> 3) + 2];
    __shared__ float2 grp2[NGRP + 1];
    __shared__ float  red_s[8], red_q[8];
    __shared__ float2 s_scsh[2];   /* [ch].x=scale, .y=shift */

    const int tile = blockIdx.x;
    const int cc   = blockIdx.y;
    const int b    = blockIdx.z;
    const int tid  = threadIdx.x;
    const int t0   = tile * TC;

    /* ---- inline stats: threads 0-127 -> channel 2cc, 128-255 -> 2cc+1 ---- */
    {
        const int half = tid >> 7;
        const int ch   = 2 * cc + half;
        const int li   = tid & 127;
        float s = 0.f, q = 0.f;
        if (li < NP_)       { s += g_ps[ch * NP_ + li];       q += g_pq[ch * NP_ + li]; }
        if (li + 128 < NP_) { s += g_ps[ch * NP_ + li + 128]; q += g_pq[ch * NP_ + li + 128]; }
#pragma unroll
        for (int o = 16; o; o >>= 1) {
            s += __shfl_down_sync(0xffffffffu, s, o);
            q += __shfl_down_sync(0xffffffffu, q, o);
        }
        const int w = tid >> 5, l = tid & 31;
        if (l == 0) { red_s[w] = s; red_q[w] = q; }
        __syncthreads();
        if (tid < 2) {
            float S = red_s[4 * tid] + red_s[4 * tid + 1] + red_s[4 * tid + 2] + red_s[4 * tid + 3];
            float Q = red_q[4 * tid] + red_q[4 * tid + 1] + red_q[4 * tid + 2] + red_q[4 * tid + 3];
            const float n    = (float)B_ * (float)T1;
            const float mean = S / n;
            const float var  = Q / n - mean * mean;
            const int ch2    = 2 * cc + tid;
            const float scv  = gamma[ch2] * rsqrtf(var + 1e-5f);
            s_scsh[tid] = make_float2(scv, beta[ch2] - mean * scv);
        }
        __syncthreads();
    }

    const float2 sc = make_float2(s_scsh[0].x, s_scsh[1].x);
    const float2 sh = make_float2(s_scsh[0].y, s_scsh[1].y);
    const __half* __restrict__ yp0 = g_yh + ((size_t)(b * C_ + 2 * cc)) * T1P;
    const __half* __restrict__ yp1 = yp0 + T1P;

    for (int j = tid; j < NGRP; j += THC) {
        const int i0 = 8 * j;
        const int gt = t0 + i0;
        float2 gs = make_float2(0.f, 0.f);
        if (gt + 7 < T1 && i0 + 7 < NAC) {
            uint4 u0 = *reinterpret_cast<const uint4*>(yp0 + gt);
            uint4 u1 = *reinterpret_cast<const uint4*>(yp1 + gt);
            const __half2* h0 = reinterpret_cast<const __half2*>(&u0);
            const __half2* h1 = reinterpret_cast<const __half2*>(&u1);
#pragma unroll
            for (int p = 0; p < 4; ++p) {
                float2 v0 = __half22float2(h0[p]);
                float2 v1 = __half22float2(h1[p]);
                float2 va = make_float2(fabsf(fmaf(v0.x, sc.x, sh.x)),
                                        fabsf(fmaf(v1.x, sc.y, sh.y)));
                float2 vb = make_float2(fabsf(fmaf(v0.y, sc.x, sh.x)),
                                        fabsf(fmaf(v1.y, sc.y, sh.y)));
                sa2[swz8(i0 + 2 * p)]     = va;
                sa2[swz8(i0 + 2 * p + 1)] = vb;
                gs.x += va.x + vb.x;
                gs.y += va.y + vb.y;
            }
        } else {
#pragma unroll
            for (int e = 0; e < 8; ++e) {
                if (i0 + e < NAC) {
                    float a0 = (gt + e < T1) ? __half2float(yp0[gt + e]) : 0.f;
                    float a1 = (gt + e < T1) ? __half2float(yp1[gt + e]) : 0.f;
                    float2 v = make_float2(fabsf(fmaf(a0, sc.x, sh.x)),
                                           fabsf(fmaf(a1, sc.y, sh.y)));
                    sa2[swz8(i0 + e)] = v;
                    gs.x += v.x;
                    gs.y += v.y;
                }
            }
        }
        grp2[j] = gs;
    }
    __syncthreads();

    const int base = tid * RC;
    const float wl0 = w_low[(2 * cc) * K2];
    const float wl1 = w_low[(2 * cc + 1) * K2];
    const float bl0 = b_low[2 * cc];
    const float bl1 = b_low[2 * cc + 1];

    float2 s;
    {
        float2 g0 = grp2[tid],     g1 = grp2[tid + 1];
        float2 g2 = grp2[tid + 2], g3 = grp2[tid + 3];
        float2 g4 = grp2[tid + 4], g5 = grp2[tid + 5];
        float2 e0 = sa2[swz8(base + 48)];
        float2 e1 = sa2[swz8(base + 49)];
        s.x = ((g0.x + g1.x) + (g2.x + g3.x)) + ((g4.x + g5.x) + (e0.x + e1.x));
        s.y = ((g0.y + g1.y) + (g2.y + g3.y)) + ((g4.y + g5.y) + (e0.y + e1.y));
    }

    float2 z[RC];
    z[0] = s;
#pragma unroll
    for (int r = 1; r < RC; ++r) {
        float2 a = sa2[swz8(base + r + K2 - 1)];
        float2 d = sa2[swz8(base + r - 1)];
        s.x += a.x - d.x;
        s.y += a.y - d.y;
        z[r] = s;
    }

    float* __restrict__ o0 = out + ((size_t)(b * C_ + 2 * cc)) * T2 + t0 + base;
    float* __restrict__ o1 = o0 + T2;

    if (t0 + TC <= T2) {
        float4* __restrict__ o0v = reinterpret_cast<float4*>(o0);
        float4* __restrict__ o1v = reinterpret_cast<float4*>(o1);
#pragma unroll
        for (int g2i = 0; g2i < RC / 4; ++g2i) {
            o0v[g2i] = make_float4(fmaf(z[4 * g2i].x, wl0, bl0), fmaf(z[4 * g2i + 1].x, wl0, bl0),
                                   fmaf(z[4 * g2i + 2].x, wl0, bl0), fmaf(z[4 * g2i + 3].x, wl0, bl0));
            o1v[g2i] = make_float4(fmaf(z[4 * g2i].y, wl1, bl1), fmaf(z[4 * g2i + 1].y, wl1, bl1),
                                   fmaf(z[4 * g2i + 2].y, wl1, bl1), fmaf(z[4 * g2i + 3].y, wl1, bl1));
        }
    } else {
#pragma unroll
        for (int r = 0; r < RC; ++r) {
            if (t0 + base + r < T2) {
                o0[r] = fmaf(z[r].x, wl0, bl0);
                o1[r] = fmaf(z[r].y, wl1, bl1);
            }
        }
    }
}

/* ===================================================================== */
extern "C" void kernel_launch(void* const* d_in, const int* in_sizes, int n_in,
                              void* d_out, int out_size)
{
    const float* x      = (const float*)d_in[0];
    const float* w_band = (const float*)d_in[1];
    const float* gamma  = (const float*)d_in[2];
    const float* beta   = (const float*)d_in[3];
    const float* w_low  = (const float*)d_in[4];
    const float* b_low  = (const float*)d_in[5];
    float* out = (float*)d_out;

    dim3 ga(NTILE_A, C_, B_);
    conv_band_mma<<<ga, THA>>>(x, w_band);

    dim3 gc(NTILE_C, CP, B_);
    lowpass_kernel<<<gc, THC>>>(gamma, beta, w_low, b_low, out);
}